// round 12
// baseline (speedup 1.0000x reference)
#include <cuda_runtime.h>
#include <math.h>

#define B_ 32
#define J_ 1024
#define D_ 192
#define E_ 384
#define N_ 16
#define M_ (B_*J_)   // 32768 rows

// ---------------- scratch (static __device__, no runtime alloc) ----------------
__device__ __align__(16) float g_t   [M_*D_];
__device__ __align__(16) float g_x   [M_*E_];
__device__ __align__(16) float g_gate[M_*E_];
__device__ __align__(16) float g_Ab  [2*M_*N_];
__device__ __align__(16) float g_Bu  [2*M_*N_];
__device__ __align__(16) float g_Ct  [2*M_*N_];
__device__ __align__(16) float g_S2  [M_*32];    // [row][Sf(16)|Sb(16)]
__device__ __align__(16) float g_Yg  [M_*E_];
__device__ __align__(16) float g_Wf  [E_*64];
__device__ __align__(16) float g_Wb  [E_*64];
__device__ __align__(16) float g_Wr2 [32*E_];    // [Wr; Wr] stacked along K
__device__ __align__(16) float g_bf  [64];
__device__ __align__(16) float g_bb  [64];
__device__ __align__(16) float g_Aneg[N_];

__device__ __forceinline__ float softplusf(float x) {
    return x > 20.f ? x : log1pf(expf(x));
}

// ---- pack proj weights (col c = 4n+{B,C,D,u}); stack Wr; A = -softplus(A_log) ----
__global__ void prep_pack(const float* __restrict__ WBf, const float* __restrict__ WCf,
                          const float* __restrict__ WDf, const float* __restrict__ WBb,
                          const float* __restrict__ WCb, const float* __restrict__ WDb,
                          const float* __restrict__ Wi, const float* __restrict__ Wr,
                          const float* __restrict__ A_log) {
    int i = blockIdx.x * blockDim.x + threadIdx.x;
    if (i < E_*64) {
        int e = i >> 6, c = i & 63;
        int n = c >> 2, q = c & 3;
        const float* sf = (q == 0) ? WBf : (q == 1) ? WCf : (q == 2) ? WDf : Wi;
        const float* sb = (q == 0) ? WBb : (q == 1) ? WCb : (q == 2) ? WDb : Wi;
        g_Wf[i] = sf[e*N_ + n];
        g_Wb[i] = sb[e*N_ + n];
    }
    if (i < 32*E_) {
        int k = i / E_, e = i - k*E_;
        g_Wr2[i] = Wr[(k & 15)*E_ + e];
    }
    if (i < N_) g_Aneg[i] = -softplusf(A_log[i]);
}

// ---- fold conv bias into projection bias: b_eff = b + cb @ Wpack (exact) --------
__global__ void prep_bias(const float* __restrict__ bBf, const float* __restrict__ bCf,
                          const float* __restrict__ bDf, const float* __restrict__ bBb,
                          const float* __restrict__ bCb, const float* __restrict__ bDb,
                          const float* __restrict__ bi,
                          const float* __restrict__ cbf, const float* __restrict__ cbb) {
    int t = threadIdx.x;
    int dir = t >> 6, c = t & 63;
    int n = c >> 2, q = c & 3;
    const float* bs = dir ? ((q==0)?bBb:(q==1)?bCb:(q==2)?bDb:bi)
                          : ((q==0)?bBf:(q==1)?bCf:(q==2)?bDf:bi);
    const float* Wp = dir ? g_Wb : g_Wf;
    const float* cb = dir ? cbb  : cbf;
    float s = bs[n];
    for (int e = 0; e < E_; e++) s = fmaf(cb[e], Wp[e*64 + c], s);
    (dir ? g_bb : g_bf)[c] = s;
}

// ---------------- LayerNorm: one warp per row ------------------------------------
__global__ void ln_kernel(const float* __restrict__ tok, const float* __restrict__ gw,
                          const float* __restrict__ gb) {
    int warp = (blockIdx.x * blockDim.x + threadIdx.x) >> 5;
    int lane = threadIdx.x & 31;
    if (warp >= M_) return;
    const float* r = tok + (size_t)warp * D_;
    float v[6];
    float s = 0.f;
#pragma unroll
    for (int i = 0; i < 6; i++) { v[i] = r[lane + i*32]; s += v[i]; }
#pragma unroll
    for (int o = 16; o; o >>= 1) s += __shfl_xor_sync(0xffffffffu, s, o);
    float mu = s * (1.f / D_);
    float q = 0.f;
#pragma unroll
    for (int i = 0; i < 6; i++) { float d = v[i] - mu; q += d * d; }
#pragma unroll
    for (int o = 16; o; o >>= 1) q += __shfl_xor_sync(0xffffffffu, q, o);
    float rs = rsqrtf(q * (1.f / D_) + 1e-5f);
    float* o = g_t + (size_t)warp * D_;
#pragma unroll
    for (int i = 0; i < 6; i++) {
        int c = lane + i*32;
        o[c] = (v[i] - mu) * rs * gw[c] + gb[c];
    }
}

// ---------------- GEMM: BM=128, BK=16, 8x8 microtile, FFMA2 paired along M -------
// As transposed [k][m] (m-pairs contiguous); Ws duplicated [k][2*BN] (b-dup pairs).
enum { EPI_PLAIN = 0, EPI_GATE = 1, EPI_MUL = 2, EPI_ADD = 3, EPI_SSM = 4 };

template <int KD, int ND, int BN, int EPI, int CONV>
__global__ void __launch_bounds__(16*(BN/8), (BN == 128) ? 2 : 3) gemm_k(
    const float* __restrict__ A, const float* __restrict__ W,
    const float* __restrict__ bias, float bscale,
    const float* __restrict__ aux, float* __restrict__ C,
    const float* __restrict__ cw, int ssm_base)
{
    constexpr int BM = 128, BK = 16;
    constexpr int TX = BN / 8;       // 16 or 8
    constexpr int NT = 16 * TX;      // 256 or 128
    constexpr int HN = BN / 2;
    constexpr int WQ = BN / 8;       // W cols per loader thread (interleaved by 8)
    extern __shared__ float dsm[];
    float* AsB = dsm;                       // [2][BK][BM]
    float* WsB = dsm + 2*BK*BM;             // [2][BK][2*BN]
    float* cws = WsB + 2*BK*2*BN;           // [3*KD] if CONV

    int tid = threadIdx.x;
    int tx = tid % TX, ty = tid / TX;
    int row0 = blockIdx.y * BM, col0 = blockIdx.x * BN;

    if (CONV) {
        for (int i = tid; i < 3*KD; i += NT) cws[i] = cw[i];
        __syncthreads();
    }

    float regA[16];
    float regW[WQ];

    auto loadA = [&](int k0) {
        int row = row0 + tid;            // callers guarantee tid < 128
        if (CONV == 0) {
#pragma unroll
            for (int q = 0; q < 4; q++)
                *(float4*)&regA[q*4] = *(const float4*)&A[(size_t)row*KD + k0 + q*4];
        } else {
            int j = row & (J_ - 1);
            const float* xr = A + (size_t)row*KD + k0;
            float4 z4 = make_float4(0.f, 0.f, 0.f, 0.f);
#pragma unroll
            for (int q = 0; q < 4; q++) {
                float4 x0 = *(const float4*)&xr[q*4];
                float4 xm = (j > 0)      ? *(const float4*)&xr[q*4 - KD] : z4;
                float4 xp = (j < J_ - 1) ? *(const float4*)&xr[q*4 + KD] : z4;
#pragma unroll
                for (int i = 0; i < 4; i++) {
                    int e = k0 + q*4 + i;
                    float w0 = cws[e*3], w1 = cws[e*3+1], w2 = cws[e*3+2];
                    float a = (&x0.x)[i], m = (&xm.x)[i], p = (&xp.x)[i];
                    regA[q*4+i] = (CONV == 1)
                        ? fmaf(w0, m, fmaf(w1, a, w2 * p))
                        : fmaf(w0, p, fmaf(w1, a, w2 * m));
                }
            }
        }
    };

    auto loadW = [&](int k0) {
        int t = (BN == 128) ? (tid - 128) : tid;
        int wk = t >> 3, o = t & 7;
#pragma unroll
        for (int q = 0; q < WQ; q++)
            regW[q] = W[(size_t)(k0 + wk) * ND + col0 + o + 8*q];
    };

    auto load_tile = [&](int k0) {
        if (BN == 128) {
            if (tid < 128) loadA(k0); else loadW(k0);
        } else {
            loadA(k0); loadW(k0);
        }
    };

    auto store_tile = [&](int buf) {
        if (BN == 64 || tid < 128) {
#pragma unroll
            for (int k = 0; k < BK; k++) AsB[(buf*BK + k)*BM + tid] = regA[k];
        }
        if (BN == 64 || tid >= 128) {
            int t = (BN == 128) ? (tid - 128) : tid;
            int wk = t >> 3, o = t & 7;
#pragma unroll
            for (int q = 0; q < WQ; q++) {
                float w = regW[q];
                *(float2*)&WsB[(buf*BK + wk)*(2*BN) + 2*(o + 8*q)] = make_float2(w, w);
            }
        }
    };

    // accp[mp][j]: row-pair mp (2 adjacent M rows) x column j
    unsigned long long accp[4][8] = {};

    load_tile(0);
    store_tile(0);
    __syncthreads();
    int buf = 0;
    for (int k0 = BK; k0 <= KD; k0 += BK) {
        bool has_next = (k0 < KD);
        if (has_next) load_tile(k0);
#pragma unroll
        for (int kk = 0; kk < BK; kk++) {
            const float* asr = &AsB[(buf*BK + kk)*BM];
            const float* wsr = &WsB[(buf*BK + kk)*(2*BN)];
            ulonglong2 a01 = *(const ulonglong2*)&asr[ty*4];
            ulonglong2 a23 = *(const ulonglong2*)&asr[64 + ty*4];
            unsigned long long ap[4];
            ap[0] = a01.x; ap[1] = a01.y; ap[2] = a23.x; ap[3] = a23.y;
            ulonglong2 b01 = *(const ulonglong2*)&wsr[8*tx];
            ulonglong2 b23 = *(const ulonglong2*)&wsr[8*tx + 4];
            ulonglong2 c01 = *(const ulonglong2*)&wsr[2*HN + 8*tx];
            ulonglong2 c23 = *(const ulonglong2*)&wsr[2*HN + 8*tx + 4];
            unsigned long long bd[8];
            bd[0] = b01.x; bd[1] = b01.y; bd[2] = b23.x; bd[3] = b23.y;
            bd[4] = c01.x; bd[5] = c01.y; bd[6] = c23.x; bd[7] = c23.y;
#pragma unroll
            for (int mp = 0; mp < 4; mp++)
#pragma unroll
                for (int j = 0; j < 8; j++)
                    asm("fma.rn.f32x2 %0, %1, %2, %0;"
                        : "+l"(accp[mp][j]) : "l"(ap[mp]), "l"(bd[j]));
        }
        if (has_next) {
            store_tile(buf ^ 1);
            __syncthreads();
            buf ^= 1;
        }
    }

    // -------- epilogue: row-pair mp holds rows (lo, hi) --------
#pragma unroll
    for (int mp = 0; mp < 4; mp++) {
        int rbase = row0 + ty*4 + (mp & 1)*2 + (mp >> 1)*64;
#pragma unroll
        for (int lh = 0; lh < 2; lh++) {
            int row = rbase + lh;
            float accf[8];
#pragma unroll
            for (int j = 0; j < 8; j++) {
                unsigned int r0, r1;
                asm("mov.b64 {%0, %1}, %2;" : "=r"(r0), "=r"(r1) : "l"(accp[mp][j]));
                accf[j] = __uint_as_float(lh ? r1 : r0);
            }
            if (EPI == EPI_SSM) {
#pragma unroll
                for (int h = 0; h < 2; h++) {
                    int n = h*8 + tx;
                    float vB = accf[h*4+0] + bias[h*32 + tx*4 + 0];
                    float vC = accf[h*4+1] + bias[h*32 + tx*4 + 1];
                    float vD = accf[h*4+2] + bias[h*32 + tx*4 + 2];
                    float vu = accf[h*4+3] + bias[h*32 + tx*4 + 3];
                    float Dt = softplusf(vD);
                    float Aa = g_Aneg[n];
                    float ab = __expf(Dt * Aa);
                    float bu = (ab - 1.f) / (Aa + 1e-6f) * vB * vu;
                    int idx = ssm_base + row*N_ + n;
                    g_Ab[idx] = ab;
                    g_Bu[idx] = bu;
                    g_Ct[idx] = vC;
                }
            } else {
#pragma unroll
                for (int h = 0; h < 2; h++) {
                    int col = col0 + h*HN + tx*4;
                    size_t co = (size_t)row * ND + col;
                    float4 xv;
                    if (EPI == EPI_MUL || EPI == EPI_ADD) xv = *(const float4*)&aux[co];
                    float o[4];
#pragma unroll
                    for (int q = 0; q < 4; q++) {
                        float v = accf[h*4+q] + bscale * bias[col + q];
                        if (EPI == EPI_GATE) {
                            float sg = 1.f / (1.f + __expf(-v));
                            float si = v * sg;
                            v = 1.f / (1.f + __expf(-si));
                        } else if (EPI == EPI_MUL) {
                            v *= (&xv.x)[q];
                        } else if (EPI == EPI_ADD) {
                            v += (&xv.x)[q];
                        }
                        o[q] = v;
                    }
                    *(float4*)&C[co] = *(float4*)o;
                }
            }
        }
    }
}

// ------- sequential scan: one warp per (dir, b); writes [row][Sf|Sb] layout -------
__global__ void scan_kernel() {
    int wg   = blockIdx.x;
    int lane = threadIdx.x;
    if (lane >= N_) return;
    int dir = wg & 1, b = wg >> 1;
    int rbase = dir * M_ * N_ + b * J_ * N_ + lane;
    int rstep = dir ? -N_ : N_;
    int ridx  = dir ? (rbase + (J_ - 1) * N_) : rbase;
    int sbase = b * J_ * 32 + dir * 16 + lane;
    int sstep = dir ? -32 : 32;
    int sidx  = dir ? (sbase + (J_ - 1) * 32) : sbase;

    const int U = 4;
    float ab[U], bu[U], ct[U];
#pragma unroll
    for (int u = 0; u < U; u++) {
        int i2 = ridx + u * rstep;
        ab[u] = g_Ab[i2]; bu[u] = g_Bu[i2]; ct[u] = g_Ct[i2];
    }
    float h = 0.f;
    for (int j0 = 0; j0 < J_; j0 += U) {
        float nab[U], nbu[U], nct[U];
        if (j0 + U < J_) {
#pragma unroll
            for (int u = 0; u < U; u++) {
                int i2 = ridx + (U + u) * rstep;
                nab[u] = g_Ab[i2]; nbu[u] = g_Bu[i2]; nct[u] = g_Ct[i2];
            }
        }
#pragma unroll
        for (int u = 0; u < U; u++) {
            h = fmaf(ab[u], h, bu[u]);
            g_S2[sidx + u * sstep] = h * ct[u];
        }
#pragma unroll
        for (int u = 0; u < U; u++) { ab[u] = nab[u]; bu[u] = nbu[u]; ct[u] = nct[u]; }
        ridx += U * rstep;
        sidx += U * sstep;
    }
}

// ---------------- launch ----------------------------------------------------------
extern "C" void kernel_launch(void* const* d_in, const int* in_sizes, int n_in,
                              void* d_out, int out_size) {
    const float* tokens  = (const float*)d_in[0];
    const float* norm_g  = (const float*)d_in[1];
    const float* norm_b  = (const float*)d_in[2];
    const float* Wx      = (const float*)d_in[3];
    const float* bx      = (const float*)d_in[4];
    const float* Wz      = (const float*)d_in[5];
    const float* bz      = (const float*)d_in[6];
    const float* convf_w = (const float*)d_in[7];
    const float* convf_b = (const float*)d_in[8];
    const float* convb_w = (const float*)d_in[9];
    const float* convb_b = (const float*)d_in[10];
    const float* WBf = (const float*)d_in[11];
    const float* bBf = (const float*)d_in[12];
    const float* WCf = (const float*)d_in[13];
    const float* bCf = (const float*)d_in[14];
    const float* WDf = (const float*)d_in[15];
    const float* bDf = (const float*)d_in[16];
    const float* WBb = (const float*)d_in[17];
    const float* bBb = (const float*)d_in[18];
    const float* WCb = (const float*)d_in[19];
    const float* bCb = (const float*)d_in[20];
    const float* WDb = (const float*)d_in[21];
    const float* bDb = (const float*)d_in[22];
    const float* A_log = (const float*)d_in[23];
    const float* Wi  = (const float*)d_in[24];
    const float* bi  = (const float*)d_in[25];
    const float* Wr  = (const float*)d_in[26];
    const float* br  = (const float*)d_in[27];
    const float* Wo  = (const float*)d_in[28];
    const float* bo  = (const float*)d_in[29];

    float *p_t, *p_x, *p_gate, *p_Wf, *p_Wb, *p_Wr2, *p_bf, *p_bb, *p_S2, *p_Yg;
    cudaGetSymbolAddress((void**)&p_t,    g_t);
    cudaGetSymbolAddress((void**)&p_x,    g_x);
    cudaGetSymbolAddress((void**)&p_gate, g_gate);
    cudaGetSymbolAddress((void**)&p_Wf,   g_Wf);
    cudaGetSymbolAddress((void**)&p_Wb,   g_Wb);
    cudaGetSymbolAddress((void**)&p_Wr2,  g_Wr2);
    cudaGetSymbolAddress((void**)&p_bf,   g_bf);
    cudaGetSymbolAddress((void**)&p_bb,   g_bb);
    cudaGetSymbolAddress((void**)&p_S2,   g_S2);
    cudaGetSymbolAddress((void**)&p_Yg,   g_Yg);

    const size_t smem128 = (size_t)(2*16*128 + 2*16*256) * sizeof(float);          // 49152
    const size_t smem64c = (size_t)(2*16*128 + 2*16*128 + 3*E_) * sizeof(float);   // 37376
    const size_t smem64  = (size_t)(2*16*128 + 2*16*128) * sizeof(float);          // 32768

    prep_pack<<<96, 256>>>(WBf, WCf, WDf, WBb, WCb, WDb, Wi, Wr, A_log);
    prep_bias<<<1, 128>>>(bBf, bCf, bDf, bBb, bCb, bDb, bi, convf_b, convb_b);
    ln_kernel<<<M_/8, 256>>>(tokens, norm_g, norm_b);

    // x = t@Wx + bx ; gate = sigmoid(silu(t@Wz + bz))
    gemm_k<D_, E_, 128, EPI_PLAIN, 0><<<dim3(E_/128, M_/128), 256, smem128>>>(
        p_t, Wx, bx, 1.f, nullptr, p_x, nullptr, 0);
    gemm_k<D_, E_, 128, EPI_GATE, 0><<<dim3(E_/128, M_/128), 256, smem128>>>(
        p_t, Wz, bz, 1.f, nullptr, p_gate, nullptr, 0);

    // fused conv + packed projections + ZOH discretization (per direction)
    gemm_k<E_, 64, 64, EPI_SSM, 1><<<dim3(1, M_/128), 128, smem64c>>>(
        p_x, p_Wf, p_bf, 1.f, nullptr, nullptr, convf_w, 0);
    gemm_k<E_, 64, 64, EPI_SSM, 2><<<dim3(1, M_/128), 128, smem64c>>>(
        p_x, p_Wb, p_bb, 1.f, nullptr, nullptr, convb_w, M_*N_);

    scan_kernel<<<64, 32>>>();

    // Yg = ([Sf|Sb] @ [Wr;Wr] + 2*br) * gate   (K=32, no dual-A load)
    gemm_k<32, E_, 128, EPI_MUL, 0><<<dim3(E_/128, M_/128), 256, smem128>>>(
        p_S2, p_Wr2, br, 2.f, p_gate, p_Yg, nullptr, 0);
    // out = tokens + Yg @ Wo + bo
    gemm_k<E_, D_, 64, EPI_ADD, 0><<<dim3(D_/64, M_/128), 128, smem64>>>(
        p_Yg, Wo, bo, 1.f, tokens, (float*)d_out, nullptr, 0);
}

// round 13
// speedup vs baseline: 1.5608x; 1.5608x over previous
#include <cuda_runtime.h>
#include <math.h>

#define B_ 32
#define J_ 1024
#define D_ 192
#define E_ 384
#define N_ 16
#define M_ (B_*J_)   // 32768 rows

// ---------------- scratch (static __device__, no runtime alloc) ----------------
__device__ __align__(16) float g_t   [M_*D_];
__device__ __align__(16) float g_x   [M_*E_];
__device__ __align__(16) float g_gate[M_*E_];
__device__ __align__(16) float g_Ab  [2*M_*N_];
__device__ __align__(16) float g_Bu  [2*M_*N_];
__device__ __align__(16) float g_Ct  [2*M_*N_];
__device__ __align__(16) float g_S2  [M_*32];    // [row][Sf(16)|Sb(16)]
__device__ __align__(16) float g_Yg  [M_*E_];
__device__ __align__(16) float g_Wf  [E_*64];
__device__ __align__(16) float g_Wb  [E_*64];
__device__ __align__(16) float g_Wr2 [32*E_];    // [Wr; Wr] stacked along K
__device__ __align__(16) float g_bf  [64];
__device__ __align__(16) float g_bb  [64];
__device__ __align__(16) float g_Aneg[N_];

__device__ __forceinline__ float softplusf(float x) {
    return x > 20.f ? x : log1pf(expf(x));
}

// ---- pack proj weights (col c = 4n+{B,C,D,u}); stack Wr; A = -softplus(A_log) ----
__global__ void prep_pack(const float* __restrict__ WBf, const float* __restrict__ WCf,
                          const float* __restrict__ WDf, const float* __restrict__ WBb,
                          const float* __restrict__ WCb, const float* __restrict__ WDb,
                          const float* __restrict__ Wi, const float* __restrict__ Wr,
                          const float* __restrict__ A_log) {
    int i = blockIdx.x * blockDim.x + threadIdx.x;
    if (i < E_*64) {
        int e = i >> 6, c = i & 63;
        int n = c >> 2, q = c & 3;
        const float* sf = (q == 0) ? WBf : (q == 1) ? WCf : (q == 2) ? WDf : Wi;
        const float* sb = (q == 0) ? WBb : (q == 1) ? WCb : (q == 2) ? WDb : Wi;
        g_Wf[i] = sf[e*N_ + n];
        g_Wb[i] = sb[e*N_ + n];
    }
    if (i < 32*E_) {
        int k = i / E_, e = i - k*E_;
        g_Wr2[i] = Wr[(k & 15)*E_ + e];
    }
    if (i < N_) g_Aneg[i] = -softplusf(A_log[i]);
}

// ---- fold conv bias into projection bias: b_eff = b + cb @ Wpack (exact) --------
__global__ void prep_bias(const float* __restrict__ bBf, const float* __restrict__ bCf,
                          const float* __restrict__ bDf, const float* __restrict__ bBb,
                          const float* __restrict__ bCb, const float* __restrict__ bDb,
                          const float* __restrict__ bi,
                          const float* __restrict__ cbf, const float* __restrict__ cbb) {
    int t = threadIdx.x;
    int dir = t >> 6, c = t & 63;
    int n = c >> 2, q = c & 3;
    const float* bs = dir ? ((q==0)?bBb:(q==1)?bCb:(q==2)?bDb:bi)
                          : ((q==0)?bBf:(q==1)?bCf:(q==2)?bDf:bi);
    const float* Wp = dir ? g_Wb : g_Wf;
    const float* cb = dir ? cbb  : cbf;
    float s = bs[n];
    for (int e = 0; e < E_; e++) s = fmaf(cb[e], Wp[e*64 + c], s);
    (dir ? g_bb : g_bf)[c] = s;
}

// ---------------- LayerNorm: one warp per row ------------------------------------
__global__ void ln_kernel(const float* __restrict__ tok, const float* __restrict__ gw,
                          const float* __restrict__ gb) {
    int warp = (blockIdx.x * blockDim.x + threadIdx.x) >> 5;
    int lane = threadIdx.x & 31;
    if (warp >= M_) return;
    const float* r = tok + (size_t)warp * D_;
    float v[6];
    float s = 0.f;
#pragma unroll
    for (int i = 0; i < 6; i++) { v[i] = r[lane + i*32]; s += v[i]; }
#pragma unroll
    for (int o = 16; o; o >>= 1) s += __shfl_xor_sync(0xffffffffu, s, o);
    float mu = s * (1.f / D_);
    float q = 0.f;
#pragma unroll
    for (int i = 0; i < 6; i++) { float d = v[i] - mu; q += d * d; }
#pragma unroll
    for (int o = 16; o; o >>= 1) q += __shfl_xor_sync(0xffffffffu, q, o);
    float rs = rsqrtf(q * (1.f / D_) + 1e-5f);
    float* o = g_t + (size_t)warp * D_;
#pragma unroll
    for (int i = 0; i < 6; i++) {
        int c = lane + i*32;
        o[c] = (v[i] - mu) * rs * gw[c] + gb[c];
    }
}

// ---------------- GEMM: BM=128, BN in {64,128}, BK=16, 8x8 microtile --------------
// FFMA2 paired along N (R11 structure): b-pairs free from shared, a-dup JIT movs.
enum { EPI_PLAIN = 0, EPI_GATE = 1, EPI_MUL = 2, EPI_ADD = 3, EPI_SSM = 4 };

template <int KD, int ND, int BN, int EPI, int CONV>
__global__ void __launch_bounds__(16*(BN/8), (BN == 128) ? 2 : 3) gemm_k(
    const float* __restrict__ A, const float* __restrict__ W,
    const float* __restrict__ bias, float bscale,
    const float* __restrict__ aux, float* __restrict__ C,
    const float* __restrict__ cw, int ssm_base)
{
    constexpr int BM = 128, BK = 16;
    constexpr int TX = BN / 8;       // thread cols (16 or 8)
    constexpr int NT = 16 * TX;      // 256 or 128 threads
    constexpr int HN = BN / 2;
    __shared__ float As[2][BK][BM];
    __shared__ float Ws[2][BK][BN];
    __shared__ float cws[CONV ? 3*KD : 4];

    int tid = threadIdx.x;
    int tx = tid % TX, ty = tid / TX;
    int row0 = blockIdx.y * BM, col0 = blockIdx.x * BN;

    if (CONV) {
        for (int i = tid; i < 3*KD; i += NT) cws[i] = cw[i];
        __syncthreads();
    }

    float regA[16];
    float regW[16];

    auto loadA = [&](int k0) {
        int row = row0 + tid;   // only called for tid < 128
        if (CONV == 0) {
#pragma unroll
            for (int q = 0; q < 4; q++)
                *(float4*)&regA[q*4] = *(const float4*)&A[(size_t)row*KD + k0 + q*4];
        } else {
            int j = row & (J_ - 1);
            const float* xr = A + (size_t)row*KD + k0;
            float4 z4 = make_float4(0.f, 0.f, 0.f, 0.f);
#pragma unroll
            for (int q = 0; q < 4; q++) {
                float4 x0 = *(const float4*)&xr[q*4];
                float4 xm = (j > 0)      ? *(const float4*)&xr[q*4 - KD] : z4;
                float4 xp = (j < J_ - 1) ? *(const float4*)&xr[q*4 + KD] : z4;
#pragma unroll
                for (int i = 0; i < 4; i++) {
                    int e = k0 + q*4 + i;
                    float w0 = cws[e*3], w1 = cws[e*3+1], w2 = cws[e*3+2];
                    float a = (&x0.x)[i], m = (&xm.x)[i], p = (&xp.x)[i];
                    regA[q*4+i] = (CONV == 1)
                        ? fmaf(w0, m, fmaf(w1, a, w2 * p))
                        : fmaf(w0, p, fmaf(w1, a, w2 * m));
                }
            }
        }
    };

    auto load_tile = [&](int k0) {
        if (BN == 128) {
            if (tid < 128) {
                loadA(k0);
            } else {
                int t = tid - 128;
                int wk = t >> 3, wn = (t & 7) * 16;
#pragma unroll
                for (int q = 0; q < 4; q++)
                    *(float4*)&regW[q*4] = *(const float4*)&W[(size_t)(k0+wk)*ND + col0 + wn + q*4];
            }
        } else {
            loadA(k0);
            int wk = tid >> 3, wn = (tid & 7) * 8;
            *(float4*)&regW[0] = *(const float4*)&W[(size_t)(k0+wk)*ND + col0 + wn];
            *(float4*)&regW[4] = *(const float4*)&W[(size_t)(k0+wk)*ND + col0 + wn + 4];
        }
    };

    auto store_tile = [&](int buf) {
        if (BN == 128) {
            if (tid < 128) {
#pragma unroll
                for (int k = 0; k < BK; k++) As[buf][k][tid] = regA[k];
            } else {
                int t = tid - 128;
                int wk = t >> 3, wn = (t & 7) * 16;
#pragma unroll
                for (int q = 0; q < 4; q++)
                    *(float4*)&Ws[buf][wk][wn + q*4] = *(float4*)&regW[q*4];
            }
        } else {
#pragma unroll
            for (int k = 0; k < BK; k++) As[buf][k][tid] = regA[k];
            int wk = tid >> 3, wn = (tid & 7) * 8;
            *(float4*)&Ws[buf][wk][wn]     = *(float4*)&regW[0];
            *(float4*)&Ws[buf][wk][wn + 4] = *(float4*)&regW[4];
        }
    };

    // packed accumulators: accp[i][jp] holds columns (2*jp, 2*jp+1) of logical row i
    unsigned long long accp[8][4] = {};

    load_tile(0);
    store_tile(0);
    __syncthreads();
    int buf = 0;
    for (int k0 = BK; k0 <= KD; k0 += BK) {
        bool has_next = (k0 < KD);
        if (has_next) load_tile(k0);
#pragma unroll
        for (int kk = 0; kk < BK; kk++) {
            float a[8];
            *(float4*)&a[0] = *(const float4*)&As[buf][kk][ty*4];
            *(float4*)&a[4] = *(const float4*)&As[buf][kk][64 + ty*4];
            ulonglong2 b01 = *(const ulonglong2*)&Ws[buf][kk][tx*4];
            ulonglong2 b23 = *(const ulonglong2*)&Ws[buf][kk][HN + tx*4];
            unsigned long long bp[4];
            bp[0] = b01.x; bp[1] = b01.y; bp[2] = b23.x; bp[3] = b23.y;
#pragma unroll
            for (int i = 0; i < 8; i++) {
                // JIT a-duplicate: live range of one register pair
                unsigned long long ai;
                unsigned int u = __float_as_uint(a[i]);
                asm("mov.b64 %0, {%1, %2};" : "=l"(ai) : "r"(u), "r"(u));
#pragma unroll
                for (int jp = 0; jp < 4; jp++)
                    asm("fma.rn.f32x2 %0, %1, %2, %0;"
                        : "+l"(accp[i][jp]) : "l"(ai), "l"(bp[jp]));
            }
        }
        if (has_next) {
            store_tile(buf ^ 1);
            __syncthreads();
            buf ^= 1;
        }
    }

    // -------- epilogue --------
#pragma unroll
    for (int rr = 0; rr < 8; rr++) {
        int row = row0 + ty*4 + (rr & 3) + ((rr >> 2) * 64);
        float accf[8];
#pragma unroll
        for (int jp = 0; jp < 4; jp++) {
            unsigned int r0, r1;
            asm("mov.b64 {%0, %1}, %2;" : "=r"(r0), "=r"(r1) : "l"(accp[rr][jp]));
            accf[2*jp]   = __uint_as_float(r0);
            accf[2*jp+1] = __uint_as_float(r1);
        }
        if (EPI == EPI_SSM) {
#pragma unroll
            for (int h = 0; h < 2; h++) {
                int n = h*8 + tx;
                float vB = accf[h*4+0] + bias[h*32 + tx*4 + 0];
                float vC = accf[h*4+1] + bias[h*32 + tx*4 + 1];
                float vD = accf[h*4+2] + bias[h*32 + tx*4 + 2];
                float vu = accf[h*4+3] + bias[h*32 + tx*4 + 3];
                float Dt = softplusf(vD);
                float Aa = g_Aneg[n];
                float ab = __expf(Dt * Aa);
                float bu = (ab - 1.f) / (Aa + 1e-6f) * vB * vu;
                int idx = ssm_base + row*N_ + n;
                g_Ab[idx] = ab;
                g_Bu[idx] = bu;
                g_Ct[idx] = vC;
            }
        } else {
#pragma unroll
            for (int h = 0; h < 2; h++) {
                int col = col0 + h*HN + tx*4;
                size_t co = (size_t)row * ND + col;
                float4 xv;
                if (EPI == EPI_MUL || EPI == EPI_ADD) xv = *(const float4*)&aux[co];
                float o[4];
#pragma unroll
                for (int q = 0; q < 4; q++) {
                    float v = accf[h*4+q] + bscale * bias[col + q];
                    if (EPI == EPI_GATE) {
                        float sg = 1.f / (1.f + __expf(-v));
                        float si = v * sg;
                        v = 1.f / (1.f + __expf(-si));
                    } else if (EPI == EPI_MUL) {
                        v *= (&xv.x)[q];
                    } else if (EPI == EPI_ADD) {
                        v += (&xv.x)[q];
                    }
                    o[q] = v;
                }
                *(float4*)&C[co] = *(float4*)o;
            }
        }
    }
}

// ------- sequential scan: one warp per (dir, b); writes [row][Sf|Sb] layout -------
__global__ void scan_kernel() {
    int wg   = blockIdx.x;
    int lane = threadIdx.x;
    if (lane >= N_) return;
    int dir = wg & 1, b = wg >> 1;
    int rbase = dir * M_ * N_ + b * J_ * N_ + lane;
    int rstep = dir ? -N_ : N_;
    int ridx  = dir ? (rbase + (J_ - 1) * N_) : rbase;
    int sbase = b * J_ * 32 + dir * 16 + lane;
    int sstep = dir ? -32 : 32;
    int sidx  = dir ? (sbase + (J_ - 1) * 32) : sbase;

    const int U = 4;
    float ab[U], bu[U], ct[U];
#pragma unroll
    for (int u = 0; u < U; u++) {
        int i2 = ridx + u * rstep;
        ab[u] = g_Ab[i2]; bu[u] = g_Bu[i2]; ct[u] = g_Ct[i2];
    }
    float h = 0.f;
    for (int j0 = 0; j0 < J_; j0 += U) {
        float nab[U], nbu[U], nct[U];
        if (j0 + U < J_) {
#pragma unroll
            for (int u = 0; u < U; u++) {
                int i2 = ridx + (U + u) * rstep;
                nab[u] = g_Ab[i2]; nbu[u] = g_Bu[i2]; nct[u] = g_Ct[i2];
            }
        }
#pragma unroll
        for (int u = 0; u < U; u++) {
            h = fmaf(ab[u], h, bu[u]);
            g_S2[sidx + u * sstep] = h * ct[u];
        }
#pragma unroll
        for (int u = 0; u < U; u++) { ab[u] = nab[u]; bu[u] = nbu[u]; ct[u] = nct[u]; }
        ridx += U * rstep;
        sidx += U * sstep;
    }
}

// ---------------- launch ----------------------------------------------------------
extern "C" void kernel_launch(void* const* d_in, const int* in_sizes, int n_in,
                              void* d_out, int out_size) {
    const float* tokens  = (const float*)d_in[0];
    const float* norm_g  = (const float*)d_in[1];
    const float* norm_b  = (const float*)d_in[2];
    const float* Wx      = (const float*)d_in[3];
    const float* bx      = (const float*)d_in[4];
    const float* Wz      = (const float*)d_in[5];
    const float* bz      = (const float*)d_in[6];
    const float* convf_w = (const float*)d_in[7];
    const float* convf_b = (const float*)d_in[8];
    const float* convb_w = (const float*)d_in[9];
    const float* convb_b = (const float*)d_in[10];
    const float* WBf = (const float*)d_in[11];
    const float* bBf = (const float*)d_in[12];
    const float* WCf = (const float*)d_in[13];
    const float* bCf = (const float*)d_in[14];
    const float* WDf = (const float*)d_in[15];
    const float* bDf = (const float*)d_in[16];
    const float* WBb = (const float*)d_in[17];
    const float* bBb = (const float*)d_in[18];
    const float* WCb = (const float*)d_in[19];
    const float* bCb = (const float*)d_in[20];
    const float* WDb = (const float*)d_in[21];
    const float* bDb = (const float*)d_in[22];
    const float* A_log = (const float*)d_in[23];
    const float* Wi  = (const float*)d_in[24];
    const float* bi  = (const float*)d_in[25];
    const float* Wr  = (const float*)d_in[26];
    const float* br  = (const float*)d_in[27];
    const float* Wo  = (const float*)d_in[28];
    const float* bo  = (const float*)d_in[29];

    float *p_t, *p_x, *p_gate, *p_Wf, *p_Wb, *p_Wr2, *p_bf, *p_bb, *p_S2, *p_Yg;
    cudaGetSymbolAddress((void**)&p_t,    g_t);
    cudaGetSymbolAddress((void**)&p_x,    g_x);
    cudaGetSymbolAddress((void**)&p_gate, g_gate);
    cudaGetSymbolAddress((void**)&p_Wf,   g_Wf);
    cudaGetSymbolAddress((void**)&p_Wb,   g_Wb);
    cudaGetSymbolAddress((void**)&p_Wr2,  g_Wr2);
    cudaGetSymbolAddress((void**)&p_bf,   g_bf);
    cudaGetSymbolAddress((void**)&p_bb,   g_bb);
    cudaGetSymbolAddress((void**)&p_S2,   g_S2);
    cudaGetSymbolAddress((void**)&p_Yg,   g_Yg);

    prep_pack<<<96, 256>>>(WBf, WCf, WDf, WBb, WCb, WDb, Wi, Wr, A_log);
    prep_bias<<<1, 128>>>(bBf, bCf, bDf, bBb, bCb, bDb, bi, convf_b, convb_b);
    ln_kernel<<<M_/8, 256>>>(tokens, norm_g, norm_b);

    // x = t@Wx + bx ; gate = sigmoid(silu(t@Wz + bz))
    gemm_k<D_, E_, 128, EPI_PLAIN, 0><<<dim3(E_/128, M_/128), 256>>>(
        p_t, Wx, bx, 1.f, nullptr, p_x, nullptr, 0);
    gemm_k<D_, E_, 128, EPI_GATE, 0><<<dim3(E_/128, M_/128), 256>>>(
        p_t, Wz, bz, 1.f, nullptr, p_gate, nullptr, 0);

    // fused conv + packed projections + ZOH discretization (per direction)
    gemm_k<E_, 64, 64, EPI_SSM, 1><<<dim3(1, M_/128), 128>>>(
        p_x, p_Wf, p_bf, 1.f, nullptr, nullptr, convf_w, 0);
    gemm_k<E_, 64, 64, EPI_SSM, 2><<<dim3(1, M_/128), 128>>>(
        p_x, p_Wb, p_bb, 1.f, nullptr, nullptr, convb_w, M_*N_);

    scan_kernel<<<64, 32>>>();

    // Yg = ([Sf|Sb] @ [Wr;Wr] + 2*br) * gate   (K=32, no dual-A load)
    gemm_k<32, E_, 128, EPI_MUL, 0><<<dim3(E_/128, M_/128), 256>>>(
        p_S2, p_Wr2, br, 2.f, p_gate, p_Yg, nullptr, 0);
    // out = tokens + Yg @ Wo + bo
    gemm_k<E_, D_, 64, EPI_ADD, 0><<<dim3(D_/64, M_/128), 128>>>(
        p_Yg, Wo, bo, 1.f, tokens, (float*)d_out, nullptr, 0);
}